// round 1
// baseline (speedup 1.0000x reference)
#include <cuda_runtime.h>

#define F    128
#define F4   32
#define NMAX 50000

// Scratch (allocation-free rule: __device__ globals)
__device__ __align__(16) float g_y[NMAX * F];      // SpMM accumulator, 25.6 MB
__device__ __align__(16) float g_sum[F];
__device__ __align__(16) float g_sumsq[F];

// ---------------------------------------------------------------------------
__global__ void zero_stats_k() {
    int t = threadIdx.x;
    if (t < F) { g_sum[t] = 0.0f; g_sumsq[t] = 0.0f; }
}

// y = (1 + eps) * x   (residual folded into the scatter accumulator init)
__global__ void init_y_k(const float4* __restrict__ x4,
                         const float* __restrict__ eps, int n4) {
    int i = blockIdx.x * blockDim.x + threadIdx.x;
    if (i >= n4) return;
    float s = 1.0f + eps[0];
    float4 v = x4[i];
    v.x *= s; v.y *= s; v.z *= s; v.w *= s;
    ((float4*)g_y)[i] = v;
}

// One warp per edge: gather x[src] (float4/lane), scale, vector-RED into y[dst]
__global__ void scatter_k(const float4* __restrict__ x4,
                          const float* __restrict__ ew,
                          const int* __restrict__ src,
                          const int* __restrict__ dst, int E) {
    int gt = blockIdx.x * blockDim.x + threadIdx.x;
    int e = gt >> 5;
    if (e >= E) return;
    int lane = gt & 31;
    int s = src[e];
    int d = dst[e];
    float w = ew[e];
    float4 v = x4[(long)s * F4 + lane];
    float4* p = ((float4*)g_y) + (long)d * F4 + lane;
    asm volatile("red.global.add.v4.f32 [%0], {%1, %2, %3, %4};"
                 :: "l"(p), "f"(v.x * w), "f"(v.y * w), "f"(v.z * w), "f"(v.w * w)
                 : "memory");
}

// ---------------------------------------------------------------------------
// Fused: h1 = relu(y @ W1 + b1); h2 = h1 @ W2 + b2 -> out; BN column partials.
// Block: 256 threads, 64-row tile. smem: W (128x128) + tile (64x128) = 96 KB.
__global__ void __launch_bounds__(256, 2)
gemm_k(const float4* __restrict__ W1, const float* __restrict__ b1,
       const float4* __restrict__ W2, const float* __restrict__ b2,
       float4* __restrict__ out4, int N) {
    extern __shared__ float smem[];
    float*  wsm  = smem;              // 128*128 floats (64 KB)
    float*  tsm  = smem + F * F;      // 64*128 floats (32 KB)
    float4* wsm4 = (float4*)wsm;
    float4* tsm4 = (float4*)tsm;

    int tid = threadIdx.x;
    int tx  = tid & 31;               // 4 output cols: tx*4 .. tx*4+3
    int ty  = tid >> 5;               // 8 rows: ty*8 .. ty*8+7
    int row0 = blockIdx.x * 64;

    // Load W1 and the y tile
    for (int i = tid; i < F * F4; i += 256) wsm4[i] = W1[i];
    for (int i = tid; i < 64 * F4; i += 256) {
        int r = row0 + (i >> 5);
        tsm4[i] = (r < N) ? ((const float4*)g_y)[(long)r * F4 + (i & 31)]
                          : make_float4(0.f, 0.f, 0.f, 0.f);
    }
    __syncthreads();

    float acc[8][4];
    {
        float4 bb = ((const float4*)b1)[tx];
        #pragma unroll
        for (int i = 0; i < 8; i++) {
            acc[i][0] = bb.x; acc[i][1] = bb.y; acc[i][2] = bb.z; acc[i][3] = bb.w;
        }
    }

    // GEMM1: acc += tile @ W1
    #pragma unroll 4
    for (int k4 = 0; k4 < F4; k4++) {
        float4 wv[4];
        #pragma unroll
        for (int kk = 0; kk < 4; kk++) wv[kk] = wsm4[(k4 * 4 + kk) * F4 + tx];
        #pragma unroll
        for (int i = 0; i < 8; i++) {
            float4 yv = tsm4[(ty * 8 + i) * F4 + k4];
            float yf[4] = {yv.x, yv.y, yv.z, yv.w};
            #pragma unroll
            for (int kk = 0; kk < 4; kk++) {
                acc[i][0] = fmaf(yf[kk], wv[kk].x, acc[i][0]);
                acc[i][1] = fmaf(yf[kk], wv[kk].y, acc[i][1]);
                acc[i][2] = fmaf(yf[kk], wv[kk].z, acc[i][2]);
                acc[i][3] = fmaf(yf[kk], wv[kk].w, acc[i][3]);
            }
        }
    }

    // ReLU
    #pragma unroll
    for (int i = 0; i < 8; i++)
        #pragma unroll
        for (int j = 0; j < 4; j++)
            acc[i][j] = fmaxf(acc[i][j], 0.0f);

    __syncthreads();   // everyone done reading wsm/tsm

    // h1 -> tsm, W2 -> wsm
    #pragma unroll
    for (int i = 0; i < 8; i++)
        tsm4[(ty * 8 + i) * F4 + tx] =
            make_float4(acc[i][0], acc[i][1], acc[i][2], acc[i][3]);
    for (int i = tid; i < F * F4; i += 256) wsm4[i] = W2[i];
    __syncthreads();

    float acc2[8][4];
    {
        float4 bb = ((const float4*)b2)[tx];
        #pragma unroll
        for (int i = 0; i < 8; i++) {
            acc2[i][0] = bb.x; acc2[i][1] = bb.y; acc2[i][2] = bb.z; acc2[i][3] = bb.w;
        }
    }

    // GEMM2: acc2 += h1 @ W2
    #pragma unroll 4
    for (int k4 = 0; k4 < F4; k4++) {
        float4 wv[4];
        #pragma unroll
        for (int kk = 0; kk < 4; kk++) wv[kk] = wsm4[(k4 * 4 + kk) * F4 + tx];
        #pragma unroll
        for (int i = 0; i < 8; i++) {
            float4 yv = tsm4[(ty * 8 + i) * F4 + k4];
            float yf[4] = {yv.x, yv.y, yv.z, yv.w};
            #pragma unroll
            for (int kk = 0; kk < 4; kk++) {
                acc2[i][0] = fmaf(yf[kk], wv[kk].x, acc2[i][0]);
                acc2[i][1] = fmaf(yf[kk], wv[kk].y, acc2[i][1]);
                acc2[i][2] = fmaf(yf[kk], wv[kk].z, acc2[i][2]);
                acc2[i][3] = fmaf(yf[kk], wv[kk].w, acc2[i][3]);
            }
        }
    }

    // Store h2 (pre-BN) + accumulate column partials (mask phantom rows)
    float cs[4] = {0.f, 0.f, 0.f, 0.f};
    float cq[4] = {0.f, 0.f, 0.f, 0.f};
    #pragma unroll
    for (int i = 0; i < 8; i++) {
        int r = row0 + ty * 8 + i;
        if (r < N) {
            out4[(long)r * F4 + tx] =
                make_float4(acc2[i][0], acc2[i][1], acc2[i][2], acc2[i][3]);
            #pragma unroll
            for (int j = 0; j < 4; j++) {
                cs[j] += acc2[i][j];
                cq[j] += acc2[i][j] * acc2[i][j];
            }
        }
    }

    __syncthreads();   // done reading smem; reuse wsm for the reduction
    #pragma unroll
    for (int j = 0; j < 4; j++) {
        wsm[ty * F + tx * 4 + j]        = cs[j];
        wsm[8 * F + ty * F + tx * 4 + j] = cq[j];
    }
    __syncthreads();
    if (tid < F) {
        float s = 0.f, q = 0.f;
        #pragma unroll
        for (int t = 0; t < 8; t++) {
            s += wsm[t * F + tid];
            q += wsm[8 * F + t * F + tid];
        }
        atomicAdd(&g_sum[tid], s);
        atomicAdd(&g_sumsq[tid], q);
    }
}

// ---------------------------------------------------------------------------
// BN normalize in place: out = (h - mean) * rsqrt(var + eps) * gamma + beta
__global__ void bn_k(float4* __restrict__ out4,
                     const float4* __restrict__ gamma4,
                     const float4* __restrict__ beta4, int N) {
    int i = blockIdx.x * blockDim.x + threadIdx.x;
    if (i >= N * F4) return;
    int c = i & 31;
    float4 s = ((const float4*)g_sum)[c];
    float4 q = ((const float4*)g_sumsq)[c];
    float4 g = gamma4[c];
    float4 b = beta4[c];
    float invN = 1.0f / (float)N;
    float4 v = out4[i];

    float m, var, is;
    m = s.x * invN; var = q.x * invN - m * m; is = rsqrtf(var + 1e-5f);
    v.x = (v.x - m) * is * g.x + b.x;
    m = s.y * invN; var = q.y * invN - m * m; is = rsqrtf(var + 1e-5f);
    v.y = (v.y - m) * is * g.y + b.y;
    m = s.z * invN; var = q.z * invN - m * m; is = rsqrtf(var + 1e-5f);
    v.z = (v.z - m) * is * g.z + b.z;
    m = s.w * invN; var = q.w * invN - m * m; is = rsqrtf(var + 1e-5f);
    v.w = (v.w - m) * is * g.w + b.w;

    out4[i] = v;
}

// ---------------------------------------------------------------------------
extern "C" void kernel_launch(void* const* d_in, const int* in_sizes, int n_in,
                              void* d_out, int out_size) {
    const float* x     = (const float*)d_in[0];
    const float* ew    = (const float*)d_in[1];
    const float* W1    = (const float*)d_in[2];
    const float* b1    = (const float*)d_in[3];
    const float* W2    = (const float*)d_in[4];
    const float* b2    = (const float*)d_in[5];
    const float* eps   = (const float*)d_in[6];
    const float* gamma = (const float*)d_in[7];
    const float* beta  = (const float*)d_in[8];
    const int*   src   = (const int*)d_in[9];
    const int*   dst   = (const int*)d_in[10];

    int N = in_sizes[0] / F;
    int E = in_sizes[1];
    float* out = (float*)d_out;

    // Idempotent; called every time (no static guards).
    cudaFuncSetAttribute(gemm_k, cudaFuncAttributeMaxDynamicSharedMemorySize,
                         (F * F + 64 * F) * (int)sizeof(float));

    zero_stats_k<<<1, 128>>>();

    int n4 = N * F4;
    init_y_k<<<(n4 + 255) / 256, 256>>>((const float4*)x, eps, n4);

    long sth = (long)E * 32;
    scatter_k<<<(int)((sth + 255) / 256), 256>>>((const float4*)x, ew, src, dst, E);

    int nblk = (N + 63) / 64;
    gemm_k<<<nblk, 256, (F * F + 64 * F) * (int)sizeof(float)>>>(
        (const float4*)W1, b1, (const float4*)W2, b2, (float4*)out, N);

    bn_k<<<(n4 + 255) / 256, 256>>>((float4*)out, (const float4*)gamma,
                                    (const float4*)beta, N);
}

// round 2
// speedup vs baseline: 1.2728x; 1.2728x over previous
#include <cuda_runtime.h>

#define F     128
#define F4    32
#define NMAX  50000
#define TROW  64          // node rows per block
#define PAD   132         // padded row length (floats) -> conflict-free fragments

// Scratch (allocation-free rule: __device__ globals)
__device__ __align__(16) float g_y[NMAX * F];      // SpMM accumulator, 25.6 MB
__device__ __align__(16) float g_sum[F];
__device__ __align__(16) float g_sumsq[F];

// ---------------------------------------------------------------------------
__global__ void zero_stats_k() {
    int t = threadIdx.x;
    if (t < F) { g_sum[t] = 0.0f; g_sumsq[t] = 0.0f; }
}

// y = (1 + eps) * x   (residual folded into the scatter accumulator init)
__global__ void init_y_k(const float4* __restrict__ x4,
                         const float* __restrict__ eps, int n4) {
    int i = blockIdx.x * blockDim.x + threadIdx.x;
    if (i >= n4) return;
    float s = 1.0f + eps[0];
    float4 v = x4[i];
    v.x *= s; v.y *= s; v.z *= s; v.w *= s;
    ((float4*)g_y)[i] = v;
}

// One warp per edge: gather x[src] (float4/lane), scale, vector-RED into y[dst]
__global__ void scatter_k(const float4* __restrict__ x4,
                          const float* __restrict__ ew,
                          const int* __restrict__ src,
                          const int* __restrict__ dst, int E) {
    int gt = blockIdx.x * blockDim.x + threadIdx.x;
    int e = gt >> 5;
    if (e >= E) return;
    int lane = gt & 31;
    int s = src[e];
    int d = dst[e];
    float w = ew[e];
    float4 v = x4[(long)s * F4 + lane];
    float4* p = ((float4*)g_y) + (long)d * F4 + lane;
    asm volatile("red.global.add.v4.f32 [%0], {%1, %2, %3, %4};"
                 :: "l"(p), "f"(v.x * w), "f"(v.y * w), "f"(v.z * w), "f"(v.w * w)
                 : "memory");
}

// ---------------------------------------------------------------------------
// tf32 helpers
__device__ __forceinline__ unsigned f2tf(float f) {
    unsigned u;
    asm("cvt.rna.tf32.f32 %0, %1;" : "=r"(u) : "f"(f));
    return u;
}

__device__ __forceinline__ void mma_tf32(float c[4],
                                         unsigned a0, unsigned a1,
                                         unsigned a2, unsigned a3,
                                         unsigned b0, unsigned b1) {
    asm volatile(
        "mma.sync.aligned.m16n8k8.row.col.f32.tf32.tf32.f32 "
        "{%0,%1,%2,%3}, {%4,%5,%6,%7}, {%8,%9}, {%0,%1,%2,%3};"
        : "+f"(c[0]), "+f"(c[1]), "+f"(c[2]), "+f"(c[3])
        : "r"(a0), "r"(a1), "r"(a2), "r"(a3), "r"(b0), "r"(b1));
}

// ---------------------------------------------------------------------------
// Fused tf32 tensor-core MLP:
//   h1 = relu(y @ W1 + b1); h2 = h1 @ W2 + b2 -> out; BN column partials.
// Block: 256 threads (8 warps). Tile: 64 nodes x 128 features.
// Warp w owns 16 output features (M of the mma); B fragments read the node
// tile row-major directly (D^T orientation).
// smem: ysm[64][132] + wsm[128][132] = 101,376 B.
__global__ void __launch_bounds__(256, 2)
gemm_tc(const float4* __restrict__ W1, const float* __restrict__ b1,
        const float4* __restrict__ W2, const float* __restrict__ b2,
        float4* __restrict__ out4, int N) {
    extern __shared__ float smem[];
    float* ysm = smem;                    // TROW x PAD
    float* wsm = smem + TROW * PAD;       // F x PAD

    int tid  = threadIdx.x;
    int lane = tid & 31;
    int w    = tid >> 5;                  // warp id 0..7
    int g    = lane >> 2;                 // 0..7
    int tig  = lane & 3;                  // 0..3
    int f0   = w * 16;                    // this warp's feature base
    int row0 = blockIdx.x * TROW;

    // ---- Stage W1 (tf32) and the y tile (tf32) ----
    for (int i = tid; i < F * F4; i += 256) {
        int k = i >> 5, c4 = (i & 31) * 4;
        float4 v = W1[i];
        float* p = wsm + k * PAD + c4;
        p[0] = __uint_as_float(f2tf(v.x));
        p[1] = __uint_as_float(f2tf(v.y));
        p[2] = __uint_as_float(f2tf(v.z));
        p[3] = __uint_as_float(f2tf(v.w));
    }
    for (int i = tid; i < TROW * F4; i += 256) {
        int r = i >> 5, c4 = (i & 31) * 4;
        int gr = row0 + r;
        float4 v = (gr < N) ? ((const float4*)g_y)[(long)gr * F4 + (i & 31)]
                            : make_float4(0.f, 0.f, 0.f, 0.f);
        float* p = ysm + r * PAD + c4;
        p[0] = __uint_as_float(f2tf(v.x));
        p[1] = __uint_as_float(f2tf(v.y));
        p[2] = __uint_as_float(f2tf(v.z));
        p[3] = __uint_as_float(f2tf(v.w));
    }
    __syncthreads();

    // ---- GEMM1: D^T[f][n] = sum_k W1[k][f] * y[n][k]  (+b1), then ReLU ----
    float acc[8][4];
    {
        float bl = b1[f0 + g], bh = b1[f0 + g + 8];
        #pragma unroll
        for (int nt = 0; nt < 8; nt++) {
            acc[nt][0] = bl; acc[nt][1] = bl; acc[nt][2] = bh; acc[nt][3] = bh;
        }
    }
    #pragma unroll
    for (int ks = 0; ks < 16; ks++) {
        int kb = ks * 8;
        unsigned a0 = __float_as_uint(wsm[(kb + tig)     * PAD + f0 + g]);
        unsigned a1 = __float_as_uint(wsm[(kb + tig)     * PAD + f0 + g + 8]);
        unsigned a2 = __float_as_uint(wsm[(kb + tig + 4) * PAD + f0 + g]);
        unsigned a3 = __float_as_uint(wsm[(kb + tig + 4) * PAD + f0 + g + 8]);
        #pragma unroll
        for (int nt = 0; nt < 8; nt++) {
            unsigned b0 = __float_as_uint(ysm[(nt * 8 + g) * PAD + kb + tig]);
            unsigned b1r = __float_as_uint(ysm[(nt * 8 + g) * PAD + kb + tig + 4]);
            mma_tf32(acc[nt], a0, a1, a2, a3, b0, b1r);
        }
    }
    #pragma unroll
    for (int nt = 0; nt < 8; nt++)
        #pragma unroll
        for (int j = 0; j < 4; j++)
            acc[nt][j] = fmaxf(acc[nt][j], 0.0f);

    __syncthreads();   // all reads of ysm/wsm done

    // ---- h1 (tf32) -> ysm[node][feat]; W2 -> wsm ----
    // c0:(f0+g, 2tig) c1:(f0+g, 2tig+1) c2:(f0+g+8, 2tig) c3:(f0+g+8, 2tig+1)
    #pragma unroll
    for (int nt = 0; nt < 8; nt++) {
        int r0r = (nt * 8 + 2 * tig) * PAD;
        int r1r = (nt * 8 + 2 * tig + 1) * PAD;
        ysm[r0r + f0 + g]     = __uint_as_float(f2tf(acc[nt][0]));
        ysm[r1r + f0 + g]     = __uint_as_float(f2tf(acc[nt][1]));
        ysm[r0r + f0 + g + 8] = __uint_as_float(f2tf(acc[nt][2]));
        ysm[r1r + f0 + g + 8] = __uint_as_float(f2tf(acc[nt][3]));
    }
    for (int i = tid; i < F * F4; i += 256) {
        int k = i >> 5, c4 = (i & 31) * 4;
        float4 v = W2[i];
        float* p = wsm + k * PAD + c4;
        p[0] = __uint_as_float(f2tf(v.x));
        p[1] = __uint_as_float(f2tf(v.y));
        p[2] = __uint_as_float(f2tf(v.z));
        p[3] = __uint_as_float(f2tf(v.w));
    }
    __syncthreads();

    // ---- GEMM2: h2^T = W2^T h1^T (+b2) ----
    {
        float bl = b2[f0 + g], bh = b2[f0 + g + 8];
        #pragma unroll
        for (int nt = 0; nt < 8; nt++) {
            acc[nt][0] = bl; acc[nt][1] = bl; acc[nt][2] = bh; acc[nt][3] = bh;
        }
    }
    #pragma unroll
    for (int ks = 0; ks < 16; ks++) {
        int kb = ks * 8;
        unsigned a0 = __float_as_uint(wsm[(kb + tig)     * PAD + f0 + g]);
        unsigned a1 = __float_as_uint(wsm[(kb + tig)     * PAD + f0 + g + 8]);
        unsigned a2 = __float_as_uint(wsm[(kb + tig + 4) * PAD + f0 + g]);
        unsigned a3 = __float_as_uint(wsm[(kb + tig + 4) * PAD + f0 + g + 8]);
        #pragma unroll
        for (int nt = 0; nt < 8; nt++) {
            unsigned b0 = __float_as_uint(ysm[(nt * 8 + g) * PAD + kb + tig]);
            unsigned b1r = __float_as_uint(ysm[(nt * 8 + g) * PAD + kb + tig + 4]);
            mma_tf32(acc[nt], a0, a1, a2, a3, b0, b1r);
        }
    }
    __syncthreads();   // all reads of ysm done

    // ---- h2 (full fp32) -> ysm[node][feat] for coalesced store ----
    #pragma unroll
    for (int nt = 0; nt < 8; nt++) {
        int r0r = (nt * 8 + 2 * tig) * PAD;
        int r1r = (nt * 8 + 2 * tig + 1) * PAD;
        ysm[r0r + f0 + g]     = acc[nt][0];
        ysm[r1r + f0 + g]     = acc[nt][1];
        ysm[r0r + f0 + g + 8] = acc[nt][2];
        ysm[r1r + f0 + g + 8] = acc[nt][3];
    }
    __syncthreads();

    // ---- Coalesced store + BN column partials (mask phantom rows) ----
    float cs[4] = {0.f, 0.f, 0.f, 0.f};
    float cq[4] = {0.f, 0.f, 0.f, 0.f};
    int c4 = tid & 31;
    #pragma unroll
    for (int j = 0; j < 8; j++) {
        int r = (tid >> 5) + j * 8;
        int gr = row0 + r;
        if (gr < N) {
            const float* p = ysm + r * PAD + c4 * 4;
            float4 v = make_float4(p[0], p[1], p[2], p[3]);
            out4[(long)gr * F4 + c4] = v;
            cs[0] += v.x; cs[1] += v.y; cs[2] += v.z; cs[3] += v.w;
            cq[0] += v.x * v.x; cq[1] += v.y * v.y;
            cq[2] += v.z * v.z; cq[3] += v.w * v.w;
        }
    }
    __syncthreads();   // done with ysm/wsm; reuse wsm for reduction
    {
        int ty = tid >> 5;
        #pragma unroll
        for (int j = 0; j < 4; j++) {
            wsm[ty * F + c4 * 4 + j]         = cs[j];
            wsm[8 * F + ty * F + c4 * 4 + j] = cq[j];
        }
    }
    __syncthreads();
    if (tid < F) {
        float s = 0.f, q = 0.f;
        #pragma unroll
        for (int t = 0; t < 8; t++) {
            s += wsm[t * F + tid];
            q += wsm[8 * F + t * F + tid];
        }
        atomicAdd(&g_sum[tid], s);
        atomicAdd(&g_sumsq[tid], q);
    }
}

// ---------------------------------------------------------------------------
// BN normalize in place: out = (h - mean) * rsqrt(var + eps) * gamma + beta
__global__ void bn_k(float4* __restrict__ out4,
                     const float4* __restrict__ gamma4,
                     const float4* __restrict__ beta4, int N) {
    int i = blockIdx.x * blockDim.x + threadIdx.x;
    if (i >= N * F4) return;
    int c = i & 31;
    float4 s = ((const float4*)g_sum)[c];
    float4 q = ((const float4*)g_sumsq)[c];
    float4 g = gamma4[c];
    float4 b = beta4[c];
    float invN = 1.0f / (float)N;
    float4 v = out4[i];

    float m, var, is;
    m = s.x * invN; var = q.x * invN - m * m; is = rsqrtf(var + 1e-5f);
    v.x = (v.x - m) * is * g.x + b.x;
    m = s.y * invN; var = q.y * invN - m * m; is = rsqrtf(var + 1e-5f);
    v.y = (v.y - m) * is * g.y + b.y;
    m = s.z * invN; var = q.z * invN - m * m; is = rsqrtf(var + 1e-5f);
    v.z = (v.z - m) * is * g.z + b.z;
    m = s.w * invN; var = q.w * invN - m * m; is = rsqrtf(var + 1e-5f);
    v.w = (v.w - m) * is * g.w + b.w;

    out4[i] = v;
}

// ---------------------------------------------------------------------------
extern "C" void kernel_launch(void* const* d_in, const int* in_sizes, int n_in,
                              void* d_out, int out_size) {
    const float* x     = (const float*)d_in[0];
    const float* ew    = (const float*)d_in[1];
    const float* W1    = (const float*)d_in[2];
    const float* b1    = (const float*)d_in[3];
    const float* W2    = (const float*)d_in[4];
    const float* b2    = (const float*)d_in[5];
    const float* eps   = (const float*)d_in[6];
    const float* gamma = (const float*)d_in[7];
    const float* beta  = (const float*)d_in[8];
    const int*   src   = (const int*)d_in[9];
    const int*   dst   = (const int*)d_in[10];

    int N = in_sizes[0] / F;
    int E = in_sizes[1];
    float* out = (float*)d_out;

    int smem_bytes = (TROW * PAD + F * PAD) * (int)sizeof(float);
    cudaFuncSetAttribute(gemm_tc, cudaFuncAttributeMaxDynamicSharedMemorySize,
                         smem_bytes);

    zero_stats_k<<<1, 128>>>();

    int n4 = N * F4;
    init_y_k<<<(n4 + 255) / 256, 256>>>((const float4*)x, eps, n4);

    long sth = (long)E * 32;
    scatter_k<<<(int)((sth + 255) / 256), 256>>>((const float4*)x, ew, src, dst, E);

    int nblk = (N + TROW - 1) / TROW;
    gemm_tc<<<nblk, 256, smem_bytes>>>(
        (const float4*)W1, b1, (const float4*)W2, b2, (float4*)out, N);

    bn_k<<<(n4 + 255) / 256, 256>>>((float4*)out, (const float4*)gamma,
                                    (const float4*)beta, N);
}

// round 3
// speedup vs baseline: 1.6201x; 1.2729x over previous
#include <cuda_runtime.h>

#define F     128
#define F4    32
#define NMAX  50000
#define EMAX  800000
#define TROW  64          // node rows per gemm block
#define PAD   132         // padded row length (floats) -> conflict-free fragments

// Scratch (allocation-free rule: __device__ globals)
__device__ __align__(16) float g_y[NMAX * F];      // aggregated features, 25.6 MB
__device__ __align__(16) float g_sum[F];
__device__ __align__(16) float g_sumsq[F];
__device__ int   g_cnt[NMAX];                      // histogram, then cursor
__device__ int   g_offs[NMAX + 1];                 // segment offsets
__device__ int   g_bsum[64];                       // scan block sums
__device__ int   g_src_s[EMAX];                    // dst-sorted edge sources
__device__ float g_w_s[EMAX];                      // dst-sorted edge weights

// ---------------------------------------------------------------------------
__global__ void zero_k(int N) {
    int i = blockIdx.x * blockDim.x + threadIdx.x;
    if (i < N) g_cnt[i] = 0;
    if (i < F) { g_sum[i] = 0.0f; g_sumsq[i] = 0.0f; }
}

__global__ void hist_k(const int* __restrict__ dst, int E) {
    int e = blockIdx.x * blockDim.x + threadIdx.x;
    if (e < E) atomicAdd(&g_cnt[dst[e]], 1);
}

// Exclusive scan of g_cnt -> g_offs (3 kernels)
__global__ void scan1_k(int N) {
    __shared__ int sh[1024];
    int t = threadIdx.x;
    int i = blockIdx.x * 1024 + t;
    int c = (i < N) ? g_cnt[i] : 0;
    sh[t] = c;
    __syncthreads();
    #pragma unroll
    for (int off = 1; off < 1024; off <<= 1) {
        int v = (t >= off) ? sh[t - off] : 0;
        __syncthreads();
        sh[t] += v;
        __syncthreads();
    }
    if (i < N) g_offs[i] = sh[t] - c;     // exclusive, block-local
    if (t == 1023) g_bsum[blockIdx.x] = sh[1023];
}

__global__ void scan2_k(int B1) {
    __shared__ int sh[64];
    int t = threadIdx.x;
    int v = (t < B1) ? g_bsum[t] : 0;
    sh[t] = v;
    __syncthreads();
    #pragma unroll
    for (int off = 1; off < 64; off <<= 1) {
        int u = (t >= off) ? sh[t - off] : 0;
        __syncthreads();
        sh[t] += u;
        __syncthreads();
    }
    if (t < B1) g_bsum[t] = sh[t] - v;    // exclusive over block totals
}

__global__ void scan3_k(int N, int E) {
    int i = blockIdx.x * blockDim.x + threadIdx.x;
    if (i < N) {
        int o = g_offs[i] + g_bsum[i >> 10];
        g_offs[i] = o;
        g_cnt[i]  = o;                    // cursor for placement
    }
    if (i == 0) g_offs[N] = E;
}

// Counting-sort placement of edges by dst
__global__ void place_k(const int* __restrict__ src,
                        const int* __restrict__ dst,
                        const float* __restrict__ ew, int E) {
    int e = blockIdx.x * blockDim.x + threadIdx.x;
    if (e >= E) return;
    int idx = atomicAdd(&g_cnt[dst[e]], 1);
    g_src_s[idx] = src[e];
    g_w_s[idx]   = ew[e];
}

// Segmented gather-reduce: one warp per dst node.
// acc initialized with the (1+eps)*x residual -> no separate init pass, no atomics.
__global__ void gather_k(const float4* __restrict__ x4,
                         const float* __restrict__ eps, int N) {
    int gt = blockIdx.x * blockDim.x + threadIdx.x;
    int d = gt >> 5;
    if (d >= N) return;
    int lane = gt & 31;

    float s1 = 1.0f + eps[0];
    float4 acc = x4[(long)d * F4 + lane];
    acc.x *= s1; acc.y *= s1; acc.z *= s1; acc.w *= s1;

    int i   = g_offs[d];
    int end = g_offs[d + 1];

    for (; i + 4 <= end; i += 4) {
        int   s0 = g_src_s[i],     s1i = g_src_s[i + 1];
        int   s2 = g_src_s[i + 2], s3  = g_src_s[i + 3];
        float w0 = g_w_s[i],       w1  = g_w_s[i + 1];
        float w2 = g_w_s[i + 2],   w3  = g_w_s[i + 3];
        float4 v0 = x4[(long)s0  * F4 + lane];
        float4 v1 = x4[(long)s1i * F4 + lane];
        float4 v2 = x4[(long)s2  * F4 + lane];
        float4 v3 = x4[(long)s3  * F4 + lane];
        acc.x = fmaf(w0, v0.x, acc.x); acc.y = fmaf(w0, v0.y, acc.y);
        acc.z = fmaf(w0, v0.z, acc.z); acc.w = fmaf(w0, v0.w, acc.w);
        acc.x = fmaf(w1, v1.x, acc.x); acc.y = fmaf(w1, v1.y, acc.y);
        acc.z = fmaf(w1, v1.z, acc.z); acc.w = fmaf(w1, v1.w, acc.w);
        acc.x = fmaf(w2, v2.x, acc.x); acc.y = fmaf(w2, v2.y, acc.y);
        acc.z = fmaf(w2, v2.z, acc.z); acc.w = fmaf(w2, v2.w, acc.w);
        acc.x = fmaf(w3, v3.x, acc.x); acc.y = fmaf(w3, v3.y, acc.y);
        acc.z = fmaf(w3, v3.z, acc.z); acc.w = fmaf(w3, v3.w, acc.w);
    }
    for (; i < end; i++) {
        int   s = g_src_s[i];
        float w = g_w_s[i];
        float4 v = x4[(long)s * F4 + lane];
        acc.x = fmaf(w, v.x, acc.x); acc.y = fmaf(w, v.y, acc.y);
        acc.z = fmaf(w, v.z, acc.z); acc.w = fmaf(w, v.w, acc.w);
    }
    ((float4*)g_y)[(long)d * F4 + lane] = acc;
}

// ---------------------------------------------------------------------------
// tf32 helpers
__device__ __forceinline__ unsigned f2tf(float f) {
    unsigned u;
    asm("cvt.rna.tf32.f32 %0, %1;" : "=r"(u) : "f"(f));
    return u;
}

__device__ __forceinline__ void mma_tf32(float c[4],
                                         unsigned a0, unsigned a1,
                                         unsigned a2, unsigned a3,
                                         unsigned b0, unsigned b1) {
    asm volatile(
        "mma.sync.aligned.m16n8k8.row.col.f32.tf32.tf32.f32 "
        "{%0,%1,%2,%3}, {%4,%5,%6,%7}, {%8,%9}, {%0,%1,%2,%3};"
        : "+f"(c[0]), "+f"(c[1]), "+f"(c[2]), "+f"(c[3])
        : "r"(a0), "r"(a1), "r"(a2), "r"(a3), "r"(b0), "r"(b1));
}

// ---------------------------------------------------------------------------
// Fused tf32 tensor-core MLP (unchanged from R2):
//   h1 = relu(y @ W1 + b1); h2 = h1 @ W2 + b2 -> out; BN column partials.
__global__ void __launch_bounds__(256, 2)
gemm_tc(const float4* __restrict__ W1, const float* __restrict__ b1,
        const float4* __restrict__ W2, const float* __restrict__ b2,
        float4* __restrict__ out4, int N) {
    extern __shared__ float smem[];
    float* ysm = smem;                    // TROW x PAD
    float* wsm = smem + TROW * PAD;       // F x PAD

    int tid  = threadIdx.x;
    int lane = tid & 31;
    int w    = tid >> 5;
    int g    = lane >> 2;
    int tig  = lane & 3;
    int f0   = w * 16;
    int row0 = blockIdx.x * TROW;

    for (int i = tid; i < F * F4; i += 256) {
        int k = i >> 5, c4 = (i & 31) * 4;
        float4 v = W1[i];
        float* p = wsm + k * PAD + c4;
        p[0] = __uint_as_float(f2tf(v.x));
        p[1] = __uint_as_float(f2tf(v.y));
        p[2] = __uint_as_float(f2tf(v.z));
        p[3] = __uint_as_float(f2tf(v.w));
    }
    for (int i = tid; i < TROW * F4; i += 256) {
        int r = i >> 5, c4 = (i & 31) * 4;
        int gr = row0 + r;
        float4 v = (gr < N) ? ((const float4*)g_y)[(long)gr * F4 + (i & 31)]
                            : make_float4(0.f, 0.f, 0.f, 0.f);
        float* p = ysm + r * PAD + c4;
        p[0] = __uint_as_float(f2tf(v.x));
        p[1] = __uint_as_float(f2tf(v.y));
        p[2] = __uint_as_float(f2tf(v.z));
        p[3] = __uint_as_float(f2tf(v.w));
    }
    __syncthreads();

    float acc[8][4];
    {
        float bl = b1[f0 + g], bh = b1[f0 + g + 8];
        #pragma unroll
        for (int nt = 0; nt < 8; nt++) {
            acc[nt][0] = bl; acc[nt][1] = bl; acc[nt][2] = bh; acc[nt][3] = bh;
        }
    }
    #pragma unroll
    for (int ks = 0; ks < 16; ks++) {
        int kb = ks * 8;
        unsigned a0 = __float_as_uint(wsm[(kb + tig)     * PAD + f0 + g]);
        unsigned a1 = __float_as_uint(wsm[(kb + tig)     * PAD + f0 + g + 8]);
        unsigned a2 = __float_as_uint(wsm[(kb + tig + 4) * PAD + f0 + g]);
        unsigned a3 = __float_as_uint(wsm[(kb + tig + 4) * PAD + f0 + g + 8]);
        #pragma unroll
        for (int nt = 0; nt < 8; nt++) {
            unsigned b0 = __float_as_uint(ysm[(nt * 8 + g) * PAD + kb + tig]);
            unsigned b1r = __float_as_uint(ysm[(nt * 8 + g) * PAD + kb + tig + 4]);
            mma_tf32(acc[nt], a0, a1, a2, a3, b0, b1r);
        }
    }
    #pragma unroll
    for (int nt = 0; nt < 8; nt++)
        #pragma unroll
        for (int j = 0; j < 4; j++)
            acc[nt][j] = fmaxf(acc[nt][j], 0.0f);

    __syncthreads();

    #pragma unroll
    for (int nt = 0; nt < 8; nt++) {
        int r0r = (nt * 8 + 2 * tig) * PAD;
        int r1r = (nt * 8 + 2 * tig + 1) * PAD;
        ysm[r0r + f0 + g]     = __uint_as_float(f2tf(acc[nt][0]));
        ysm[r1r + f0 + g]     = __uint_as_float(f2tf(acc[nt][1]));
        ysm[r0r + f0 + g + 8] = __uint_as_float(f2tf(acc[nt][2]));
        ysm[r1r + f0 + g + 8] = __uint_as_float(f2tf(acc[nt][3]));
    }
    for (int i = tid; i < F * F4; i += 256) {
        int k = i >> 5, c4 = (i & 31) * 4;
        float4 v = W2[i];
        float* p = wsm + k * PAD + c4;
        p[0] = __uint_as_float(f2tf(v.x));
        p[1] = __uint_as_float(f2tf(v.y));
        p[2] = __uint_as_float(f2tf(v.z));
        p[3] = __uint_as_float(f2tf(v.w));
    }
    __syncthreads();

    {
        float bl = b2[f0 + g], bh = b2[f0 + g + 8];
        #pragma unroll
        for (int nt = 0; nt < 8; nt++) {
            acc[nt][0] = bl; acc[nt][1] = bl; acc[nt][2] = bh; acc[nt][3] = bh;
        }
    }
    #pragma unroll
    for (int ks = 0; ks < 16; ks++) {
        int kb = ks * 8;
        unsigned a0 = __float_as_uint(wsm[(kb + tig)     * PAD + f0 + g]);
        unsigned a1 = __float_as_uint(wsm[(kb + tig)     * PAD + f0 + g + 8]);
        unsigned a2 = __float_as_uint(wsm[(kb + tig + 4) * PAD + f0 + g]);
        unsigned a3 = __float_as_uint(wsm[(kb + tig + 4) * PAD + f0 + g + 8]);
        #pragma unroll
        for (int nt = 0; nt < 8; nt++) {
            unsigned b0 = __float_as_uint(ysm[(nt * 8 + g) * PAD + kb + tig]);
            unsigned b1r = __float_as_uint(ysm[(nt * 8 + g) * PAD + kb + tig + 4]);
            mma_tf32(acc[nt], a0, a1, a2, a3, b0, b1r);
        }
    }
    __syncthreads();

    #pragma unroll
    for (int nt = 0; nt < 8; nt++) {
        int r0r = (nt * 8 + 2 * tig) * PAD;
        int r1r = (nt * 8 + 2 * tig + 1) * PAD;
        ysm[r0r + f0 + g]     = acc[nt][0];
        ysm[r1r + f0 + g]     = acc[nt][1];
        ysm[r0r + f0 + g + 8] = acc[nt][2];
        ysm[r1r + f0 + g + 8] = acc[nt][3];
    }
    __syncthreads();

    float cs[4] = {0.f, 0.f, 0.f, 0.f};
    float cq[4] = {0.f, 0.f, 0.f, 0.f};
    int c4 = tid & 31;
    #pragma unroll
    for (int j = 0; j < 8; j++) {
        int r = (tid >> 5) + j * 8;
        int gr = row0 + r;
        if (gr < N) {
            const float* p = ysm + r * PAD + c4 * 4;
            float4 v = make_float4(p[0], p[1], p[2], p[3]);
            out4[(long)gr * F4 + c4] = v;
            cs[0] += v.x; cs[1] += v.y; cs[2] += v.z; cs[3] += v.w;
            cq[0] += v.x * v.x; cq[1] += v.y * v.y;
            cq[2] += v.z * v.z; cq[3] += v.w * v.w;
        }
    }
    __syncthreads();
    {
        int ty = tid >> 5;
        #pragma unroll
        for (int j = 0; j < 4; j++) {
            wsm[ty * F + c4 * 4 + j]         = cs[j];
            wsm[8 * F + ty * F + c4 * 4 + j] = cq[j];
        }
    }
    __syncthreads();
    if (tid < F) {
        float s = 0.f, q = 0.f;
        #pragma unroll
        for (int t = 0; t < 8; t++) {
            s += wsm[t * F + tid];
            q += wsm[8 * F + t * F + tid];
        }
        atomicAdd(&g_sum[tid], s);
        atomicAdd(&g_sumsq[tid], q);
    }
}

// ---------------------------------------------------------------------------
__global__ void bn_k(float4* __restrict__ out4,
                     const float4* __restrict__ gamma4,
                     const float4* __restrict__ beta4, int N) {
    int i = blockIdx.x * blockDim.x + threadIdx.x;
    if (i >= N * F4) return;
    int c = i & 31;
    float4 s = ((const float4*)g_sum)[c];
    float4 q = ((const float4*)g_sumsq)[c];
    float4 g = gamma4[c];
    float4 b = beta4[c];
    float invN = 1.0f / (float)N;
    float4 v = out4[i];

    float m, var, is;
    m = s.x * invN; var = q.x * invN - m * m; is = rsqrtf(var + 1e-5f);
    v.x = (v.x - m) * is * g.x + b.x;
    m = s.y * invN; var = q.y * invN - m * m; is = rsqrtf(var + 1e-5f);
    v.y = (v.y - m) * is * g.y + b.y;
    m = s.z * invN; var = q.z * invN - m * m; is = rsqrtf(var + 1e-5f);
    v.z = (v.z - m) * is * g.z + b.z;
    m = s.w * invN; var = q.w * invN - m * m; is = rsqrtf(var + 1e-5f);
    v.w = (v.w - m) * is * g.w + b.w;

    out4[i] = v;
}

// ---------------------------------------------------------------------------
extern "C" void kernel_launch(void* const* d_in, const int* in_sizes, int n_in,
                              void* d_out, int out_size) {
    const float* x     = (const float*)d_in[0];
    const float* ew    = (const float*)d_in[1];
    const float* W1    = (const float*)d_in[2];
    const float* b1    = (const float*)d_in[3];
    const float* W2    = (const float*)d_in[4];
    const float* b2    = (const float*)d_in[5];
    const float* eps   = (const float*)d_in[6];
    const float* gamma = (const float*)d_in[7];
    const float* beta  = (const float*)d_in[8];
    const int*   src   = (const int*)d_in[9];
    const int*   dst   = (const int*)d_in[10];

    int N = in_sizes[0] / F;
    int E = in_sizes[1];
    float* out = (float*)d_out;

    int smem_bytes = (TROW * PAD + F * PAD) * (int)sizeof(float);
    cudaFuncSetAttribute(gemm_tc, cudaFuncAttributeMaxDynamicSharedMemorySize,
                         smem_bytes);

    int B1 = (N + 1023) / 1024;

    zero_k<<<(N + 255) / 256, 256>>>(N);
    hist_k<<<(E + 255) / 256, 256>>>(dst, E);
    scan1_k<<<B1, 1024>>>(N);
    scan2_k<<<1, 64>>>(B1);
    scan3_k<<<(N + 255) / 256, 256>>>(N, E);
    place_k<<<(E + 255) / 256, 256>>>(src, dst, ew, E);

    gather_k<<<(N * 32 + 255) / 256, 256>>>((const float4*)x, eps, N);

    int nblk = (N + TROW - 1) / TROW;
    gemm_tc<<<nblk, 256, smem_bytes>>>(
        (const float4*)W1, b1, (const float4*)W2, b2, (float4*)out, N);

    bn_k<<<(N * F4 + 255) / 256, 256>>>((float4*)out, (const float4*)gamma,
                                        (const float4*)beta, N);
}

// round 4
// speedup vs baseline: 1.6915x; 1.0441x over previous
#include <cuda_runtime.h>

#define F     128
#define F4    32
#define NMAX  50000
#define EMAX  800000
#define TROW  64          // node rows per gemm block
#define PAD   132         // padded row length (floats) -> conflict-free fragments

// Scratch (allocation-free rule: __device__ globals)
__device__ __align__(16) float g_y[NMAX * F];      // aggregated features, 25.6 MB
__device__ __align__(16) float g_sum[F];
__device__ __align__(16) float g_sumsq[F];
__device__ int   g_cnt[NMAX];                      // histogram, then cursor
__device__ int   g_offs[NMAX + 1];                 // segment offsets
__device__ int   g_bsum[64];                       // scan block sums
__device__ int   g_src_s[EMAX];                    // dst-sorted edge sources
__device__ float g_w_s[EMAX];                      // dst-sorted edge weights

// ---------------------------------------------------------------------------
__global__ void zero_k(int N) {
    int i = blockIdx.x * blockDim.x + threadIdx.x;
    if (i < N) g_cnt[i] = 0;
    if (i < F) { g_sum[i] = 0.0f; g_sumsq[i] = 0.0f; }
}

__global__ void hist_k(const int* __restrict__ dst, int E) {
    int e = blockIdx.x * blockDim.x + threadIdx.x;
    if (e < E) atomicAdd(&g_cnt[dst[e]], 1);
}

// Exclusive scan of g_cnt -> g_offs (3 kernels)
__global__ void scan1_k(int N) {
    __shared__ int sh[1024];
    int t = threadIdx.x;
    int i = blockIdx.x * 1024 + t;
    int c = (i < N) ? g_cnt[i] : 0;
    sh[t] = c;
    __syncthreads();
    #pragma unroll
    for (int off = 1; off < 1024; off <<= 1) {
        int v = (t >= off) ? sh[t - off] : 0;
        __syncthreads();
        sh[t] += v;
        __syncthreads();
    }
    if (i < N) g_offs[i] = sh[t] - c;     // exclusive, block-local
    if (t == 1023) g_bsum[blockIdx.x] = sh[1023];
}

__global__ void scan2_k(int B1) {
    __shared__ int sh[64];
    int t = threadIdx.x;
    int v = (t < B1) ? g_bsum[t] : 0;
    sh[t] = v;
    __syncthreads();
    #pragma unroll
    for (int off = 1; off < 64; off <<= 1) {
        int u = (t >= off) ? sh[t - off] : 0;
        __syncthreads();
        sh[t] += u;
        __syncthreads();
    }
    if (t < B1) g_bsum[t] = sh[t] - v;    // exclusive over block totals
}

__global__ void scan3_k(int N, int E) {
    int i = blockIdx.x * blockDim.x + threadIdx.x;
    if (i < N) {
        int o = g_offs[i] + g_bsum[i >> 10];
        g_offs[i] = o;
        g_cnt[i]  = o;                    // cursor for placement
    }
    if (i == 0) g_offs[N] = E;
}

// Counting-sort placement of edges by dst
__global__ void place_k(const int* __restrict__ src,
                        const int* __restrict__ dst,
                        const float* __restrict__ ew, int E) {
    int e = blockIdx.x * blockDim.x + threadIdx.x;
    if (e >= E) return;
    int idx = atomicAdd(&g_cnt[dst[e]], 1);
    g_src_s[idx] = src[e];
    g_w_s[idx]   = ew[e];
}

// Segmented gather-reduce: one warp per dst node.
__global__ void gather_k(const float4* __restrict__ x4,
                         const float* __restrict__ eps, int N) {
    int gt = blockIdx.x * blockDim.x + threadIdx.x;
    int d = gt >> 5;
    if (d >= N) return;
    int lane = gt & 31;

    float s1 = 1.0f + eps[0];
    float4 acc = x4[(long)d * F4 + lane];
    acc.x *= s1; acc.y *= s1; acc.z *= s1; acc.w *= s1;

    int i   = g_offs[d];
    int end = g_offs[d + 1];

    for (; i + 4 <= end; i += 4) {
        int   s0 = g_src_s[i],     s1i = g_src_s[i + 1];
        int   s2 = g_src_s[i + 2], s3  = g_src_s[i + 3];
        float w0 = g_w_s[i],       w1  = g_w_s[i + 1];
        float w2 = g_w_s[i + 2],   w3  = g_w_s[i + 3];
        float4 v0 = x4[(long)s0  * F4 + lane];
        float4 v1 = x4[(long)s1i * F4 + lane];
        float4 v2 = x4[(long)s2  * F4 + lane];
        float4 v3 = x4[(long)s3  * F4 + lane];
        acc.x = fmaf(w0, v0.x, acc.x); acc.y = fmaf(w0, v0.y, acc.y);
        acc.z = fmaf(w0, v0.z, acc.z); acc.w = fmaf(w0, v0.w, acc.w);
        acc.x = fmaf(w1, v1.x, acc.x); acc.y = fmaf(w1, v1.y, acc.y);
        acc.z = fmaf(w1, v1.z, acc.z); acc.w = fmaf(w1, v1.w, acc.w);
        acc.x = fmaf(w2, v2.x, acc.x); acc.y = fmaf(w2, v2.y, acc.y);
        acc.z = fmaf(w2, v2.z, acc.z); acc.w = fmaf(w2, v2.w, acc.w);
        acc.x = fmaf(w3, v3.x, acc.x); acc.y = fmaf(w3, v3.y, acc.y);
        acc.z = fmaf(w3, v3.z, acc.z); acc.w = fmaf(w3, v3.w, acc.w);
    }
    for (; i < end; i++) {
        int   s = g_src_s[i];
        float w = g_w_s[i];
        float4 v = x4[(long)s * F4 + lane];
        acc.x = fmaf(w, v.x, acc.x); acc.y = fmaf(w, v.y, acc.y);
        acc.z = fmaf(w, v.z, acc.z); acc.w = fmaf(w, v.w, acc.w);
    }
    ((float4*)g_y)[(long)d * F4 + lane] = acc;
}

// ---------------------------------------------------------------------------
// tf32 helpers
__device__ __forceinline__ unsigned f2tf(float f) {
    unsigned u;
    asm("cvt.rna.tf32.f32 %0, %1;" : "=r"(u) : "f"(f));
    return u;
}

__device__ __forceinline__ void mma_tf32(float c[4],
                                         unsigned a0, unsigned a1,
                                         unsigned a2, unsigned a3,
                                         unsigned b0, unsigned b1) {
    asm volatile(
        "mma.sync.aligned.m16n8k8.row.col.f32.tf32.tf32.f32 "
        "{%0,%1,%2,%3}, {%4,%5,%6,%7}, {%8,%9}, {%0,%1,%2,%3};"
        : "+f"(c[0]), "+f"(c[1]), "+f"(c[2]), "+f"(c[3])
        : "r"(a0), "r"(a1), "r"(a2), "r"(a3), "r"(b0), "r"(b1));
}

// ---------------------------------------------------------------------------
// Fused tf32 tensor-core MLP — 512 threads, 16 warps.
// Warp w: 16 features (f0 = (w&7)*16) x 32 nodes (nb = (w>>3)*32, nt=0..3).
// acc is 16 regs -> 2 CTAs/SM by registers -> 50% occupancy.
__global__ void __launch_bounds__(512, 2)
gemm_tc(const float4* __restrict__ W1, const float* __restrict__ b1,
        const float4* __restrict__ W2, const float* __restrict__ b2,
        float4* __restrict__ out4, int N) {
    extern __shared__ float smem[];
    float* ysm = smem;                    // TROW x PAD
    float* wsm = smem + TROW * PAD;       // F x PAD

    int tid  = threadIdx.x;
    int lane = tid & 31;
    int w    = tid >> 5;                  // 0..15
    int g    = lane >> 2;                 // 0..7
    int tig  = lane & 3;                  // 0..3
    int f0   = (w & 7) * 16;              // feature base
    int nb   = (w >> 3) * 32;             // node base (0 or 32)
    int row0 = blockIdx.x * TROW;

    // ---- Stage W1 (tf32) and the y tile (tf32) ----
    for (int i = tid; i < F * F4; i += 512) {
        int k = i >> 5, c4 = (i & 31) * 4;
        float4 v = W1[i];
        float* p = wsm + k * PAD + c4;
        p[0] = __uint_as_float(f2tf(v.x));
        p[1] = __uint_as_float(f2tf(v.y));
        p[2] = __uint_as_float(f2tf(v.z));
        p[3] = __uint_as_float(f2tf(v.w));
    }
    for (int i = tid; i < TROW * F4; i += 512) {
        int r = i >> 5, c4 = (i & 31) * 4;
        int gr = row0 + r;
        float4 v = (gr < N) ? ((const float4*)g_y)[(long)gr * F4 + (i & 31)]
                            : make_float4(0.f, 0.f, 0.f, 0.f);
        float* p = ysm + r * PAD + c4;
        p[0] = __uint_as_float(f2tf(v.x));
        p[1] = __uint_as_float(f2tf(v.y));
        p[2] = __uint_as_float(f2tf(v.z));
        p[3] = __uint_as_float(f2tf(v.w));
    }
    __syncthreads();

    float acc[4][4];
    {
        float bl = b1[f0 + g], bh = b1[f0 + g + 8];
        #pragma unroll
        for (int nt = 0; nt < 4; nt++) {
            acc[nt][0] = bl; acc[nt][1] = bl; acc[nt][2] = bh; acc[nt][3] = bh;
        }
    }
    #pragma unroll
    for (int ks = 0; ks < 16; ks++) {
        int kb = ks * 8;
        unsigned a0 = __float_as_uint(wsm[(kb + tig)     * PAD + f0 + g]);
        unsigned a1 = __float_as_uint(wsm[(kb + tig)     * PAD + f0 + g + 8]);
        unsigned a2 = __float_as_uint(wsm[(kb + tig + 4) * PAD + f0 + g]);
        unsigned a3 = __float_as_uint(wsm[(kb + tig + 4) * PAD + f0 + g + 8]);
        #pragma unroll
        for (int nt = 0; nt < 4; nt++) {
            unsigned b0 = __float_as_uint(ysm[(nb + nt * 8 + g) * PAD + kb + tig]);
            unsigned b1r = __float_as_uint(ysm[(nb + nt * 8 + g) * PAD + kb + tig + 4]);
            mma_tf32(acc[nt], a0, a1, a2, a3, b0, b1r);
        }
    }
    #pragma unroll
    for (int nt = 0; nt < 4; nt++)
        #pragma unroll
        for (int j = 0; j < 4; j++)
            acc[nt][j] = fmaxf(acc[nt][j], 0.0f);

    __syncthreads();   // all reads of ysm/wsm done

    // ---- h1 (tf32) -> ysm[node][feat]; W2 -> wsm ----
    #pragma unroll
    for (int nt = 0; nt < 4; nt++) {
        int r0r = (nb + nt * 8 + 2 * tig) * PAD;
        int r1r = (nb + nt * 8 + 2 * tig + 1) * PAD;
        ysm[r0r + f0 + g]     = __uint_as_float(f2tf(acc[nt][0]));
        ysm[r1r + f0 + g]     = __uint_as_float(f2tf(acc[nt][1]));
        ysm[r0r + f0 + g + 8] = __uint_as_float(f2tf(acc[nt][2]));
        ysm[r1r + f0 + g + 8] = __uint_as_float(f2tf(acc[nt][3]));
    }
    for (int i = tid; i < F * F4; i += 512) {
        int k = i >> 5, c4 = (i & 31) * 4;
        float4 v = W2[i];
        float* p = wsm + k * PAD + c4;
        p[0] = __uint_as_float(f2tf(v.x));
        p[1] = __uint_as_float(f2tf(v.y));
        p[2] = __uint_as_float(f2tf(v.z));
        p[3] = __uint_as_float(f2tf(v.w));
    }
    __syncthreads();

    {
        float bl = b2[f0 + g], bh = b2[f0 + g + 8];
        #pragma unroll
        for (int nt = 0; nt < 4; nt++) {
            acc[nt][0] = bl; acc[nt][1] = bl; acc[nt][2] = bh; acc[nt][3] = bh;
        }
    }
    #pragma unroll
    for (int ks = 0; ks < 16; ks++) {
        int kb = ks * 8;
        unsigned a0 = __float_as_uint(wsm[(kb + tig)     * PAD + f0 + g]);
        unsigned a1 = __float_as_uint(wsm[(kb + tig)     * PAD + f0 + g + 8]);
        unsigned a2 = __float_as_uint(wsm[(kb + tig + 4) * PAD + f0 + g]);
        unsigned a3 = __float_as_uint(wsm[(kb + tig + 4) * PAD + f0 + g + 8]);
        #pragma unroll
        for (int nt = 0; nt < 4; nt++) {
            unsigned b0 = __float_as_uint(ysm[(nb + nt * 8 + g) * PAD + kb + tig]);
            unsigned b1r = __float_as_uint(ysm[(nb + nt * 8 + g) * PAD + kb + tig + 4]);
            mma_tf32(acc[nt], a0, a1, a2, a3, b0, b1r);
        }
    }
    __syncthreads();   // all reads of ysm done

    // ---- h2 (full fp32) -> ysm[node][feat] for coalesced store ----
    #pragma unroll
    for (int nt = 0; nt < 4; nt++) {
        int r0r = (nb + nt * 8 + 2 * tig) * PAD;
        int r1r = (nb + nt * 8 + 2 * tig + 1) * PAD;
        ysm[r0r + f0 + g]     = acc[nt][0];
        ysm[r1r + f0 + g]     = acc[nt][1];
        ysm[r0r + f0 + g + 8] = acc[nt][2];
        ysm[r1r + f0 + g + 8] = acc[nt][3];
    }
    __syncthreads();

    // ---- Coalesced store + BN column partials (mask phantom rows) ----
    float cs[4] = {0.f, 0.f, 0.f, 0.f};
    float cq[4] = {0.f, 0.f, 0.f, 0.f};
    int c4 = tid & 31;
    int ty = tid >> 5;                    // 0..15
    #pragma unroll
    for (int j = 0; j < 4; j++) {
        int r = ty + j * 16;
        int gr = row0 + r;
        if (gr < N) {
            const float* p = ysm + r * PAD + c4 * 4;
            float4 v = make_float4(p[0], p[1], p[2], p[3]);
            out4[(long)gr * F4 + c4] = v;
            cs[0] += v.x; cs[1] += v.y; cs[2] += v.z; cs[3] += v.w;
            cq[0] += v.x * v.x; cq[1] += v.y * v.y;
            cq[2] += v.z * v.z; cq[3] += v.w * v.w;
        }
    }
    __syncthreads();   // done with ysm/wsm; reuse wsm for reduction
    #pragma unroll
    for (int j = 0; j < 4; j++) {
        wsm[ty * F + c4 * 4 + j]          = cs[j];
        wsm[16 * F + ty * F + c4 * 4 + j] = cq[j];
    }
    __syncthreads();
    if (tid < F) {
        float s = 0.f, q = 0.f;
        #pragma unroll
        for (int t = 0; t < 16; t++) {
            s += wsm[t * F + tid];
            q += wsm[16 * F + t * F + tid];
        }
        atomicAdd(&g_sum[tid], s);
        atomicAdd(&g_sumsq[tid], q);
    }
}

// ---------------------------------------------------------------------------
__global__ void bn_k(float4* __restrict__ out4,
                     const float4* __restrict__ gamma4,
                     const float4* __restrict__ beta4, int N) {
    int i = blockIdx.x * blockDim.x + threadIdx.x;
    if (i >= N * F4) return;
    int c = i & 31;
    float4 s = ((const float4*)g_sum)[c];
    float4 q = ((const float4*)g_sumsq)[c];
    float4 g = gamma4[c];
    float4 b = beta4[c];
    float invN = 1.0f / (float)N;
    float4 v = out4[i];

    float m, var, is;
    m = s.x * invN; var = q.x * invN - m * m; is = rsqrtf(var + 1e-5f);
    v.x = (v.x - m) * is * g.x + b.x;
    m = s.y * invN; var = q.y * invN - m * m; is = rsqrtf(var + 1e-5f);
    v.y = (v.y - m) * is * g.y + b.y;
    m = s.z * invN; var = q.z * invN - m * m; is = rsqrtf(var + 1e-5f);
    v.z = (v.z - m) * is * g.z + b.z;
    m = s.w * invN; var = q.w * invN - m * m; is = rsqrtf(var + 1e-5f);
    v.w = (v.w - m) * is * g.w + b.w;

    out4[i] = v;
}

// ---------------------------------------------------------------------------
extern "C" void kernel_launch(void* const* d_in, const int* in_sizes, int n_in,
                              void* d_out, int out_size) {
    const float* x     = (const float*)d_in[0];
    const float* ew    = (const float*)d_in[1];
    const float* W1    = (const float*)d_in[2];
    const float* b1    = (const float*)d_in[3];
    const float* W2    = (const float*)d_in[4];
    const float* b2    = (const float*)d_in[5];
    const float* eps   = (const float*)d_in[6];
    const float* gamma = (const float*)d_in[7];
    const float* beta  = (const float*)d_in[8];
    const int*   src   = (const int*)d_in[9];
    const int*   dst   = (const int*)d_in[10];

    int N = in_sizes[0] / F;
    int E = in_sizes[1];
    float* out = (float*)d_out;

    int smem_bytes = (TROW * PAD + F * PAD) * (int)sizeof(float);
    cudaFuncSetAttribute(gemm_tc, cudaFuncAttributeMaxDynamicSharedMemorySize,
                         smem_bytes);

    int B1 = (N + 1023) / 1024;

    zero_k<<<(N + 255) / 256, 256>>>(N);
    hist_k<<<(E + 255) / 256, 256>>>(dst, E);
    scan1_k<<<B1, 1024>>>(N);
    scan2_k<<<1, 64>>>(B1);
    scan3_k<<<(N + 255) / 256, 256>>>(N, E);
    place_k<<<(E + 255) / 256, 256>>>(src, dst, ew, E);

    gather_k<<<(N * 32 + 255) / 256, 256>>>((const float4*)x, eps, N);

    int nblk = (N + TROW - 1) / TROW;
    gemm_tc<<<nblk, 512, smem_bytes>>>(
        (const float4*)W1, b1, (const float4*)W2, b2, (float4*)out, N);

    bn_k<<<(N * F4 + 255) / 256, 256>>>((float4*)out, (const float4*)gamma,
                                        (const float4*)beta, N);
}